// round 15
// baseline (speedup 1.0000x reference)
#include <cuda_runtime.h>
#include <cstdint>

#define TOKENS 4096
#define DIN    4096
#define DOUT   4096
#define NW     (DIN * DOUT)
// jnp.quantile: index = 0.9f*(NW-1) rounds to exactly 15099493.0 in f32,
// so thr = sorted(|W|)[15099493] (0-indexed) == rank 15099494 (1-indexed).
#define RANK1  15099494u

#define CAP     704        // entries per W-row (mean 410, ~15 sigma headroom)
#define KC      128        // k-chunk
#define NCHUNK  (DIN / KC) // 32
#define RPP     33         // rowptr entries per row (NCHUNK+1)
#define NTILES  1024       // (4096/128) * (4096/128)
#define WCAP    192        // staged entries per warp-chunk (mean 102, ~9 sigma)

// ---------------------------------------------------------------------------
// Device globals (zero-initialized at module load; every kernel re-establishes
// the zero-state it consumed, so the invariant holds across graph replays)
// ---------------------------------------------------------------------------
__device__ __align__(16) float  g_xT[NW];                  // x^T  [k][m]
__device__ __align__(16) uint2  g_ent[(size_t)DOUT * CAP]; // {w_bits, (k&127)<<9}
__device__ unsigned short g_rowptr[DOUT * RPP];

#define HREP 8
__device__ unsigned g_histA[HREP][65536];
__device__ unsigned g_histB[32768];
__device__ unsigned g_ctrA, g_ctrB;
__device__ unsigned g_prefA, g_rankB;
__device__ float    g_thr;
__device__ unsigned g_tile_ctr;

__device__ __forceinline__ uint32_t smem_u32(const void* p) {
    uint32_t a;
    asm("{ .reg .u64 t; cvta.to.shared.u64 t, %1; cvt.u32.u64 %0, t; }" : "=r"(a) : "l"(p));
    return a;
}
__device__ __forceinline__ void cp16(uint32_t saddr, const void* gaddr) {
    asm volatile("cp.async.cg.shared.global [%0], [%1], 16;" :: "r"(saddr), "l"(gaddr));
}
__device__ __forceinline__ void cp_commit() {
    asm volatile("cp.async.commit_group;" ::: "memory");
}
__device__ __forceinline__ void cp_wait1() {
    asm volatile("cp.async.wait_group 1;" ::: "memory");
}
__device__ __forceinline__ float4 lds128f(uint32_t a) {
    float4 v;
    asm volatile("ld.shared.v4.f32 {%0,%1,%2,%3}, [%4];"
                 : "=f"(v.x), "=f"(v.y), "=f"(v.z), "=f"(v.w) : "r"(a));
    return v;
}
__device__ __forceinline__ uint4 lds128u(uint32_t a) {
    uint4 v;
    asm volatile("ld.shared.v4.b32 {%0,%1,%2,%3}, [%4];"
                 : "=r"(v.x), "=r"(v.y), "=r"(v.z), "=r"(v.w) : "r"(a));
    return v;
}
__device__ __forceinline__ void sts64(uint32_t a, unsigned lo, unsigned hi) {
    asm volatile("st.shared.v2.b32 [%0], {%1,%2};" :: "r"(a), "r"(lo), "r"(hi) : "memory");
}

// ---------------------------------------------------------------------------
// Launch 1: pass A — 16-bit histogram (replicated) + fused last-block scan.
// Assumes g_histA == 0 (zeroed by the previous replay's histB / initial state).
// Resets g_ctrA for the next replay.
// ---------------------------------------------------------------------------
__global__ void __launch_bounds__(256) histA_kernel(const float* __restrict__ w) {
    const int tid = threadIdx.x;
    const int rep = blockIdx.x & (HREP - 1);
    const uint4* __restrict__ w4 = reinterpret_cast<const uint4*>(w);
    const int stride = gridDim.x * blockDim.x;
    for (int i = blockIdx.x * blockDim.x + tid; i < NW / 4; i += stride) {
        uint4 v = w4[i];
        atomicAdd(&g_histA[rep][(v.x & 0x7fffffffu) >> 15], 1u);
        atomicAdd(&g_histA[rep][(v.y & 0x7fffffffu) >> 15], 1u);
        atomicAdd(&g_histA[rep][(v.z & 0x7fffffffu) >> 15], 1u);
        atomicAdd(&g_histA[rep][(v.w & 0x7fffffffu) >> 15], 1u);
    }
    __threadfence();
    __syncthreads();
    __shared__ unsigned s_last;
    if (tid == 0) s_last = (atomicAdd(&g_ctrA, 1u) == gridDim.x - 1) ? 1u : 0u;
    __syncthreads();
    if (!s_last) return;

    __shared__ unsigned csum[256];
    __shared__ unsigned s_selc, s_cumb;
    {
        unsigned ssum = 0;
        #pragma unroll
        for (int r = 0; r < HREP; r++) {
            const uint4* p = reinterpret_cast<const uint4*>(&g_histA[r][tid * 256]);
            for (int b = 0; b < 64; b++) {
                uint4 v = p[b];
                ssum += v.x + v.y + v.z + v.w;
            }
        }
        csum[tid] = ssum;
    }
    __syncthreads();
    if (tid == 0) {
        unsigned cum = 0, selc = 255;
        for (int c = 0; c < 256; c++) {
            if (cum + csum[c] >= RANK1) { selc = c; break; }
            cum += csum[c];
        }
        s_selc = selc; s_cumb = cum;
    }
    __syncthreads();
    __shared__ unsigned bsum[256];
    {
        unsigned ssum = 0;
        #pragma unroll
        for (int r = 0; r < HREP; r++) ssum += g_histA[r][s_selc * 256 + tid];
        bsum[tid] = ssum;
    }
    __syncthreads();
    if (tid == 0) {
        unsigned cum = s_cumb, sel = 255;
        for (int b = 0; b < 256; b++) {
            if (cum + bsum[b] >= RANK1) { sel = b; break; }
            cum += bsum[b];
        }
        g_prefA = s_selc * 256 + sel;
        g_rankB = RANK1 - cum;
        g_ctrA = 0u;             // re-arm for next replay
    }
}

// ---------------------------------------------------------------------------
// Launch 2: pass B — 15-bit conditional histogram + fused scan -> g_thr.
// Also zeroes g_histA (for the next replay; histB never reads it).
// Resets g_ctrB.
// ---------------------------------------------------------------------------
__global__ void __launch_bounds__(256) histB_kernel(const float* __restrict__ w) {
    const int tid = threadIdx.x;
    const int gt = blockIdx.x * blockDim.x + tid;
    const int stride = gridDim.x * blockDim.x;

    // zero g_histA for next replay (independent of this kernel's work)
    unsigned* hA = &g_histA[0][0];
    for (int i = gt; i < HREP * 65536; i += stride) hA[i] = 0u;

    const unsigned pref = g_prefA;
    const uint4* __restrict__ w4 = reinterpret_cast<const uint4*>(w);
    for (int i = gt; i < NW / 4; i += stride) {
        uint4 v = w4[i];
        unsigned a;
        a = v.x & 0x7fffffffu; if ((a >> 15) == pref) atomicAdd(&g_histB[a & 0x7fffu], 1u);
        a = v.y & 0x7fffffffu; if ((a >> 15) == pref) atomicAdd(&g_histB[a & 0x7fffu], 1u);
        a = v.z & 0x7fffffffu; if ((a >> 15) == pref) atomicAdd(&g_histB[a & 0x7fffu], 1u);
        a = v.w & 0x7fffffffu; if ((a >> 15) == pref) atomicAdd(&g_histB[a & 0x7fffu], 1u);
    }
    __threadfence();
    __syncthreads();
    __shared__ unsigned s_last;
    if (tid == 0) s_last = (atomicAdd(&g_ctrB, 1u) == gridDim.x - 1) ? 1u : 0u;
    __syncthreads();
    if (!s_last) return;

    const unsigned rankB = g_rankB;
    __shared__ unsigned csum[256];
    __shared__ unsigned s_selc, s_cumb;
    {
        unsigned ssum = 0;
        const uint4* p = reinterpret_cast<const uint4*>(&g_histB[tid * 128]);
        for (int b = 0; b < 32; b++) {
            uint4 v = p[b];
            ssum += v.x + v.y + v.z + v.w;
        }
        csum[tid] = ssum;
    }
    __syncthreads();
    if (tid == 0) {
        unsigned cum = 0, selc = 255;
        for (int c = 0; c < 256; c++) {
            if (cum + csum[c] >= rankB) { selc = c; break; }
            cum += csum[c];
        }
        s_selc = selc; s_cumb = cum;
    }
    __syncthreads();
    if (tid == 0) {
        unsigned cum = s_cumb, sel = 127;
        for (int b = 0; b < 128; b++) {
            unsigned c = g_histB[s_selc * 128 + b];
            if (cum + c >= rankB) { sel = b; break; }
            cum += c;
        }
        unsigned bits = (g_prefA << 15) | (s_selc * 128 + sel);
        g_thr = __uint_as_float(bits);
        g_ctrB = 0u;             // re-arm for next replay
    }
}

// ---------------------------------------------------------------------------
// Launch 3: fused prep — transpose x, compact pruned W rows into chunked CSR,
// zero g_histB (for next replay), reset g_tile_ctr. Ranges by blockIdx.
// ---------------------------------------------------------------------------
#define TR_BLOCKS 16384       // (DIN/32)*(TOKENS/32)
#define CP_BLOCKS 512         // DOUT/8
#define ZB_BLOCKS 64
#define PREP_BLOCKS (TR_BLOCKS + CP_BLOCKS + ZB_BLOCKS)

__global__ void __launch_bounds__(256) prep_kernel(const float* __restrict__ x,
                                                   const float* __restrict__ w) {
    const int b = blockIdx.x;
    if (b < TR_BLOCKS) {
        // transpose x -> g_xT[k][m]
        __shared__ float t[32][33];
        const int bx = b & 127;            // k tile
        const int by = b >> 7;             // m tile
        const int tx = threadIdx.x & 31;
        const int ty = threadIdx.x >> 5;   // 0..7
        const int k = bx * 32 + tx;
        const int m = by * 32 + ty;
        #pragma unroll
        for (int j = 0; j < 4; j++)
            t[ty + 8 * j][tx] = x[(size_t)(m + 8 * j) * DIN + k];
        __syncthreads();
        const int ko = bx * 32 + ty;
        const int mo = by * 32 + tx;
        #pragma unroll
        for (int j = 0; j < 4; j++)
            g_xT[(size_t)(ko + 8 * j) * TOKENS + mo] = t[tx][ty + 8 * j];
    } else if (b < TR_BLOCKS + CP_BLOCKS) {
        // compact pruned W rows (warp per row)
        const int row = (b - TR_BLOCKS) * 8 + (threadIdx.x >> 5);
        const int lane = threadIdx.x & 31;
        const float thr = g_thr;
        const float* __restrict__ wr = w + (size_t)row * DIN;
        uint2* __restrict__ pE = g_ent + (size_t)row * CAP;
        unsigned short* __restrict__ rp = g_rowptr + row * RPP;
        int base = 0;
        for (int it = 0; it < 128; it++) {
            if ((it & 3) == 0 && lane == 0) rp[it >> 2] = (unsigned short)base;
            const int k = it * 32 + lane;
            const float v = wr[k];
            const bool keep = fabsf(v) > thr;
            const unsigned m = __ballot_sync(0xffffffffu, keep);
            if (keep) {
                int idx = base + __popc(m & ((1u << lane) - 1u));
                if (idx < CAP)
                    pE[idx] = make_uint2(__float_as_uint(v),
                                         (unsigned)((k & (KC - 1)) << 9));
            }
            base += __popc(m);
        }
        if (lane == 0) rp[NCHUNK] = (unsigned short)base;
    } else {
        // zero g_histB (next replay) + reset tile counter
        const int zb = b - TR_BLOCKS - CP_BLOCKS;
        const int gt = zb * 256 + threadIdx.x;
        for (int i = gt; i < 32768; i += ZB_BLOCKS * 256) g_histB[i] = 0u;
        if (gt == 0) g_tile_ctr = 0u;
    }
}

// ---------------------------------------------------------------------------
// Launch 4 (PROFILED): sparse GEMM. Persistent CTAs, 512 threads,
// tile 128m x 128n. Warp owns 8 n-rows; lane owns m = 4*lane+q via LDS.128.
// Entries staged per-warp into smem, then broadcast-read in PAIRS via one
// LDS.128 (no shfl). xT chunk double-buffered (2 x 64KB).
// ---------------------------------------------------------------------------
#define EBUF_OFF  131072                        // 16 warps x WCAP x 8B = 24576
#define RP_OFF    (EBUF_OFF + 16 * WCAP * 8)    // 155648
#define SMEM_SPMM (RP_OFF + 8448)               // 164096

__global__ void __launch_bounds__(512, 1)
spmm_kernel(const float* __restrict__ bias, float* __restrict__ C) {
    extern __shared__ char smem[];
    const uint32_t sb = smem_u32(smem);
    unsigned short* __restrict__ s_rp =
        reinterpret_cast<unsigned short*>(smem + RP_OFF);
    __shared__ unsigned s_t;

    const int tid = threadIdx.x;
    const int wid = tid >> 5;
    const int lane = tid & 31;
    const uint32_t eb = sb + EBUF_OFF + (uint32_t)wid * (WCAP * 8);
    const uint32_t lm = (uint32_t)lane << 4;

    for (;;) {
        if (tid == 0) s_t = atomicAdd(&g_tile_ctr, 1u);
        __syncthreads();
        const unsigned t = s_t;
        if (t >= NTILES) break;
        const int m_base = (int)(t & 31) << 7;
        const int n_tile = (int)(t >> 5) << 7;
        const int n0 = n_tile + wid * 8;

        // stage rowptrs for the 128 n-rows of this tile
        {
            const unsigned short* __restrict__ src =
                g_rowptr + (size_t)n_tile * RPP;
            for (int i = tid; i < 128 * RPP; i += 512) s_rp[i] = src[i];
        }

        // prologue: chunk 0 -> buf 0
        {
            const float* __restrict__ src = g_xT + m_base;
            #pragma unroll
            for (int i = 0; i < 8; i++) {
                int f = tid + i * 512;
                int krow = f >> 5, q = f & 31;
                cp16(sb + (uint32_t)(krow * 512 + q * 16),
                     src + (size_t)krow * TOKENS + q * 4);
            }
            cp_commit();
        }

        float4 acc[8];
        #pragma unroll
        for (int r = 0; r < 8; r++) acc[r] = make_float4(0.f, 0.f, 0.f, 0.f);

        for (int c = 0; c < NCHUNK; c++) {
            if (c + 1 < NCHUNK) {
                const uint32_t dbuf = sb + (uint32_t)(((c + 1) & 1) << 16);
                const float* __restrict__ src =
                    g_xT + (size_t)(c + 1) * KC * TOKENS + m_base;
                #pragma unroll
                for (int i = 0; i < 8; i++) {
                    int f = tid + i * 512;
                    int krow = f >> 5, q = f & 31;
                    cp16(dbuf + (uint32_t)(krow * 512 + q * 16),
                         src + (size_t)krow * TOKENS + q * 4);
                }
            }
            cp_commit();
            cp_wait1();          // chunk c resident (c+1 may be in flight)
            __syncthreads();

            const uint32_t xb = sb + (uint32_t)((c & 1) << 16);

            // ---- stage this warp's 8 entry windows into smem (coalesced) ----
            int rs[8], rc2[8];
            int cur = 0;
            #pragma unroll
            for (int r = 0; r < 8; r++) {
                const int rl = wid * 8 + r;
                const int sI = s_rp[rl * RPP + c];
                const int eI = s_rp[rl * RPP + c + 1];
                int cnt = eI - sI;
                int p2 = (cnt + 1) & ~1;
                const int avail = WCAP - cur;      // always even
                if (p2 > avail) { p2 = avail; cnt = avail; }  // ~impossible
                const uint2* __restrict__ src =
                    g_ent + (size_t)(n0 + r) * CAP + sI;
                for (int e0 = lane; e0 < cnt; e0 += 32) {
                    uint2 v = src[e0];
                    sts64(eb + (uint32_t)(cur + e0) * 8u, v.x, v.y);
                }
                if ((cnt & 1) && lane == 0)
                    sts64(eb + (uint32_t)(cur + cnt) * 8u, 0u, 0u);
                rs[r] = cur;
                rc2[r] = p2;
                cur += p2;
            }
            __syncwarp();

            // ---- compute: broadcast entry pairs, LDS.128 x-data, FMA ----
            #pragma unroll
            for (int r = 0; r < 8; r++) {
                uint32_t p = eb + (uint32_t)rs[r] * 8u;
                const uint32_t pe = p + (uint32_t)rc2[r] * 8u;
                float4 a = acc[r];
                while (p < pe) {
                    const uint4 e = lds128u(p);            // {w0,off0,w1,off1}
                    const float w0 = __uint_as_float(e.x);
                    const float4 x0 = lds128f(xb + e.y + lm);
                    const float w1 = __uint_as_float(e.z);
                    const float4 x1 = lds128f(xb + e.w + lm);
                    a.x = fmaf(w0, x0.x, a.x);
                    a.y = fmaf(w0, x0.y, a.y);
                    a.z = fmaf(w0, x0.z, a.z);
                    a.w = fmaf(w0, x0.w, a.w);
                    a.x = fmaf(w1, x1.x, a.x);
                    a.y = fmaf(w1, x1.y, a.y);
                    a.z = fmaf(w1, x1.z, a.z);
                    a.w = fmaf(w1, x1.w, a.w);
                    p += 16;
                }
                acc[r] = a;
            }
            __syncthreads();   // before buffer (c+1)&1 is overwritten
        }

        // Epilogue: stage [n_local][m_local] (pitch 132, float4 stores), then
        // write C n-coalesced per m row.
        float* __restrict__ cst = reinterpret_cast<float*>(smem);
        #pragma unroll
        for (int r = 0; r < 8; r++) {
            const float bv = bias[n0 + r];
            const int nl = wid * 8 + r;
            float4 o;
            o.x = acc[r].x + bv;
            o.y = acc[r].y + bv;
            o.z = acc[r].z + bv;
            o.w = acc[r].w + bv;
            *reinterpret_cast<float4*>(&cst[nl * 132 + (lane << 2)]) = o;
        }
        __syncthreads();
        #pragma unroll
        for (int r = 0; r < 8; r++) {
            const int ml = wid * 8 + r;
            float* __restrict__ crow =
                C + (size_t)(m_base + ml) * DOUT + n_tile;
            #pragma unroll
            for (int j = 0; j < 4; j++)
                crow[lane + 32 * j] = cst[(lane + 32 * j) * 132 + ml];
        }
        __syncthreads();   // staging area becomes chunk buffer next tile
    }
}

// ---------------------------------------------------------------------------
extern "C" void kernel_launch(void* const* d_in, const int* in_sizes, int n_in,
                              void* d_out, int out_size) {
    const float* x    = (const float*)d_in[0];
    const float* w    = (const float*)d_in[1];
    const float* bias = (const float*)d_in[2];
    float* out        = (float*)d_out;

    cudaFuncSetAttribute(spmm_kernel,
                         cudaFuncAttributeMaxDynamicSharedMemorySize, SMEM_SPMM);

    histA_kernel<<<1024, 256>>>(w);                    // 1
    histB_kernel<<<1024, 256>>>(w);                    // 2
    prep_kernel<<<PREP_BLOCKS, 256>>>(x, w);           // 3
    spmm_kernel<<<148, 512, SMEM_SPMM>>>(bias, out);   // 4: profiled
}

// round 16
// speedup vs baseline: 1.7441x; 1.7441x over previous
#include <cuda_runtime.h>
#include <cstdint>

#define TOKENS 4096
#define DIN    4096
#define DOUT   4096
#define NW     (DIN * DOUT)
// jnp.quantile: index = 0.9f*(NW-1) rounds to exactly 15099493.0 in f32,
// so thr = sorted(|W|)[15099493] (0-indexed) == rank 15099494 (1-indexed).
#define RANK1  15099494u

// ---------------------------------------------------------------------------
// Device globals (zero-initialized at load; each kernel re-establishes the
// zero-state it consumed so the invariant holds across graph replays)
// ---------------------------------------------------------------------------
__device__ __align__(16) uint32_t g_xa[NW];   // x  as tf32 bit patterns
__device__ __align__(16) uint32_t g_wb[NW];   // pruned W as tf32 bit patterns

#define HREP 8
__device__ unsigned g_histA[HREP][65536];
__device__ unsigned g_histB[32768];
__device__ unsigned g_ctrA, g_ctrB;
__device__ unsigned g_prefA, g_rankB;
__device__ float    g_thr;

__device__ __forceinline__ uint32_t smem_u32(const void* p) {
    uint32_t a;
    asm("{ .reg .u64 t; cvta.to.shared.u64 t, %1; cvt.u32.u64 %0, t; }" : "=r"(a) : "l"(p));
    return a;
}
__device__ __forceinline__ void cp16(uint32_t saddr, const void* gaddr) {
    asm volatile("cp.async.cg.shared.global [%0], [%1], 16;" :: "r"(saddr), "l"(gaddr));
}
__device__ __forceinline__ void cp_commit() {
    asm volatile("cp.async.commit_group;" ::: "memory");
}
__device__ __forceinline__ void cp_wait1() {
    asm volatile("cp.async.wait_group 1;" ::: "memory");
}
__device__ __forceinline__ uint32_t lds32u(uint32_t a) {
    uint32_t v;
    asm volatile("ld.shared.b32 %0, [%1];" : "=r"(v) : "r"(a));
    return v;
}
__device__ __forceinline__ uint32_t f2tf32(float f) {
    uint32_t r;
    asm("cvt.rna.tf32.f32 %0, %1;" : "=r"(r) : "f"(f));
    return r;
}
__device__ __forceinline__ void mma_tf32(float* c, const uint32_t* a, const uint32_t* b) {
    asm volatile(
        "mma.sync.aligned.m16n8k8.row.col.f32.tf32.tf32.f32 "
        "{%0,%1,%2,%3}, {%4,%5,%6,%7}, {%8,%9}, {%0,%1,%2,%3};"
        : "+f"(c[0]), "+f"(c[1]), "+f"(c[2]), "+f"(c[3])
        : "r"(a[0]), "r"(a[1]), "r"(a[2]), "r"(a[3]), "r"(b[0]), "r"(b[1]));
}

// ---------------------------------------------------------------------------
// Launch 1: pass A — 16-bit histogram (replicated) + fused last-block scan.
// Assumes g_histA == 0 (zeroed by histB of the previous replay / initial).
// ---------------------------------------------------------------------------
__global__ void __launch_bounds__(256) histA_kernel(const float* __restrict__ w) {
    const int tid = threadIdx.x;
    const int rep = blockIdx.x & (HREP - 1);
    const uint4* __restrict__ w4 = reinterpret_cast<const uint4*>(w);
    const int stride = gridDim.x * blockDim.x;
    for (int i = blockIdx.x * blockDim.x + tid; i < NW / 4; i += stride) {
        uint4 v = w4[i];
        atomicAdd(&g_histA[rep][(v.x & 0x7fffffffu) >> 15], 1u);
        atomicAdd(&g_histA[rep][(v.y & 0x7fffffffu) >> 15], 1u);
        atomicAdd(&g_histA[rep][(v.z & 0x7fffffffu) >> 15], 1u);
        atomicAdd(&g_histA[rep][(v.w & 0x7fffffffu) >> 15], 1u);
    }
    __threadfence();
    __syncthreads();
    __shared__ unsigned s_last;
    if (tid == 0) s_last = (atomicAdd(&g_ctrA, 1u) == gridDim.x - 1) ? 1u : 0u;
    __syncthreads();
    if (!s_last) return;

    __shared__ unsigned csum[256];
    __shared__ unsigned s_selc, s_cumb;
    {
        unsigned ssum = 0;
        #pragma unroll
        for (int r = 0; r < HREP; r++) {
            const uint4* p = reinterpret_cast<const uint4*>(&g_histA[r][tid * 256]);
            for (int b = 0; b < 64; b++) {
                uint4 v = p[b];
                ssum += v.x + v.y + v.z + v.w;
            }
        }
        csum[tid] = ssum;
    }
    __syncthreads();
    if (tid == 0) {
        unsigned cum = 0, selc = 255;
        for (int c = 0; c < 256; c++) {
            if (cum + csum[c] >= RANK1) { selc = c; break; }
            cum += csum[c];
        }
        s_selc = selc; s_cumb = cum;
    }
    __syncthreads();
    __shared__ unsigned bsum[256];
    {
        unsigned ssum = 0;
        #pragma unroll
        for (int r = 0; r < HREP; r++) ssum += g_histA[r][s_selc * 256 + tid];
        bsum[tid] = ssum;
    }
    __syncthreads();
    if (tid == 0) {
        unsigned cum = s_cumb, sel = 255;
        for (int b = 0; b < 256; b++) {
            if (cum + bsum[b] >= RANK1) { sel = b; break; }
            cum += bsum[b];
        }
        g_prefA = s_selc * 256 + sel;
        g_rankB = RANK1 - cum;
        g_ctrA = 0u;             // re-arm for next replay
    }
}

// ---------------------------------------------------------------------------
// Launch 2: pass B — 15-bit conditional histogram + fused scan -> g_thr.
// Also zeroes g_histA (for the next replay).
// ---------------------------------------------------------------------------
__global__ void __launch_bounds__(256) histB_kernel(const float* __restrict__ w) {
    const int tid = threadIdx.x;
    const int gt = blockIdx.x * blockDim.x + tid;
    const int stride = gridDim.x * blockDim.x;

    unsigned* hA = &g_histA[0][0];
    for (int i = gt; i < HREP * 65536; i += stride) hA[i] = 0u;

    const unsigned pref = g_prefA;
    const uint4* __restrict__ w4 = reinterpret_cast<const uint4*>(w);
    for (int i = gt; i < NW / 4; i += stride) {
        uint4 v = w4[i];
        unsigned a;
        a = v.x & 0x7fffffffu; if ((a >> 15) == pref) atomicAdd(&g_histB[a & 0x7fffu], 1u);
        a = v.y & 0x7fffffffu; if ((a >> 15) == pref) atomicAdd(&g_histB[a & 0x7fffu], 1u);
        a = v.z & 0x7fffffffu; if ((a >> 15) == pref) atomicAdd(&g_histB[a & 0x7fffu], 1u);
        a = v.w & 0x7fffffffu; if ((a >> 15) == pref) atomicAdd(&g_histB[a & 0x7fffu], 1u);
    }
    __threadfence();
    __syncthreads();
    __shared__ unsigned s_last;
    if (tid == 0) s_last = (atomicAdd(&g_ctrB, 1u) == gridDim.x - 1) ? 1u : 0u;
    __syncthreads();
    if (!s_last) return;

    const unsigned rankB = g_rankB;
    __shared__ unsigned csum[256];
    __shared__ unsigned s_selc, s_cumb;
    {
        unsigned ssum = 0;
        const uint4* p = reinterpret_cast<const uint4*>(&g_histB[tid * 128]);
        for (int b = 0; b < 32; b++) {
            uint4 v = p[b];
            ssum += v.x + v.y + v.z + v.w;
        }
        csum[tid] = ssum;
    }
    __syncthreads();
    if (tid == 0) {
        unsigned cum = 0, selc = 255;
        for (int c = 0; c < 256; c++) {
            if (cum + csum[c] >= rankB) { selc = c; break; }
            cum += csum[c];
        }
        s_selc = selc; s_cumb = cum;
    }
    __syncthreads();
    if (tid == 0) {
        unsigned cum = s_cumb, sel = 127;
        for (int b = 0; b < 128; b++) {
            unsigned c = g_histB[s_selc * 128 + b];
            if (cum + c >= rankB) { sel = b; break; }
            cum += c;
        }
        unsigned bits = (g_prefA << 15) | (s_selc * 128 + sel);
        g_thr = __uint_as_float(bits);
        g_ctrB = 0u;             // re-arm
    }
}

// ---------------------------------------------------------------------------
// Launch 3: prep — convert x -> tf32 (RNA), prune+convert W -> tf32,
// zero g_histB for the next replay. Grid-stride over all three ranges.
// ---------------------------------------------------------------------------
__global__ void __launch_bounds__(256) prep_kernel(const float* __restrict__ x,
                                                   const float* __restrict__ w) {
    const int gt = blockIdx.x * blockDim.x + threadIdx.x;
    const int stride = gridDim.x * blockDim.x;
    const float thr = g_thr;

    const float4* __restrict__ x4 = reinterpret_cast<const float4*>(x);
    const float4* __restrict__ w4 = reinterpret_cast<const float4*>(w);
    uint4* __restrict__ xa = reinterpret_cast<uint4*>(g_xa);
    uint4* __restrict__ wb = reinterpret_cast<uint4*>(g_wb);

    for (int i = gt; i < NW / 4; i += stride) {
        float4 v = x4[i];
        uint4 o;
        o.x = f2tf32(v.x); o.y = f2tf32(v.y);
        o.z = f2tf32(v.z); o.w = f2tf32(v.w);
        xa[i] = o;
    }
    for (int i = gt; i < NW / 4; i += stride) {
        float4 v = w4[i];
        v.x = (fabsf(v.x) > thr) ? v.x : 0.0f;
        v.y = (fabsf(v.y) > thr) ? v.y : 0.0f;
        v.z = (fabsf(v.z) > thr) ? v.z : 0.0f;
        v.w = (fabsf(v.w) > thr) ? v.w : 0.0f;
        uint4 o;
        o.x = f2tf32(v.x); o.y = f2tf32(v.y);
        o.z = f2tf32(v.z); o.w = f2tf32(v.w);
        wb[i] = o;
    }
    for (int i = gt; i < 32768; i += stride) g_histB[i] = 0u;
}

// ---------------------------------------------------------------------------
// Launch 4 (PROFILED): single-term TF32 GEMM.
// C[m][n] = sum_k tf32(x)[m][k] * tf32(Wp)[n][k] + bias[n]
// BM=128, BN=256, BK=32; 256 threads (8 warps, 2x4), warp tile 64x64.
// Smem rows padded to 36 words (144B) -> conflict-free fragment LDS.32
// (banks (4g+k)%32 distinct). 3-stage cp.async pipeline.
// ---------------------------------------------------------------------------
#define ROWP    144                 // bytes per 32-float row (36 words)
#define ASTG    (128 * ROWP)        // 18432
#define BSTG    (256 * ROWP)        // 36864
#define STAGE_B (ASTG + BSTG)       // 55296
#define NSTAGE  3
#define SMEM_GEMM (NSTAGE * STAGE_B)  // 165888

__global__ void __launch_bounds__(256, 1)
gemm_tf32_kernel(const float* __restrict__ bias, float* __restrict__ C) {
    extern __shared__ char smem[];
    const uint32_t sb = smem_u32(smem);

    const int tid = threadIdx.x;
    const int wid = tid >> 5;
    const int lane = tid & 31;
    const int wm = wid & 1;        // 64-row slice of 128
    const int wn = wid >> 1;       // 64-col slice of 256
    const int m_base = blockIdx.y * 128;
    const int n_base = blockIdx.x * 256;

    auto issue_stage = [&](int it, int stg) {
        const int k0 = it * 32;
        const uint32_t base = sb + (uint32_t)stg * STAGE_B;
        #pragma unroll
        for (int i = 0; i < 4; i++) {           // A: 1024 cp16
            int f = tid + i * 256;
            int row = f >> 3, q = f & 7;
            cp16(base + (uint32_t)(row * ROWP + q * 16),
                 g_xa + (size_t)(m_base + row) * DIN + k0 + q * 4);
        }
        #pragma unroll
        for (int i = 0; i < 8; i++) {           // B: 2048 cp16
            int f = tid + i * 256;
            int row = f >> 3, q = f & 7;
            cp16(base + ASTG + (uint32_t)(row * ROWP + q * 16),
                 g_wb + (size_t)(n_base + row) * DIN + k0 + q * 4);
        }
    };

    issue_stage(0, 0); cp_commit();
    issue_stage(1, 1); cp_commit();

    float acc[4][8][4];
    #pragma unroll
    for (int mt = 0; mt < 4; mt++)
        #pragma unroll
        for (int nt = 0; nt < 8; nt++)
            #pragma unroll
            for (int q = 0; q < 4; q++) acc[mt][nt][q] = 0.0f;

    const uint32_t arow0 = (uint32_t)(wm * 64 + (lane >> 2)) * ROWP;
    const uint32_t brow0 = (uint32_t)(wn * 64 + (lane >> 2)) * ROWP;
    const uint32_t kb0 = (uint32_t)(lane & 3) * 4;

    for (int it = 0; it < DIN / 32; it++) {
        const int stg = it % NSTAGE;
        cp_wait1();
        __syncthreads();
        if (it + 2 < DIN / 32) issue_stage(it + 2, (it + 2) % NSTAGE);
        cp_commit();

        const uint32_t aA = sb + (uint32_t)stg * STAGE_B;
        const uint32_t aB = aA + ASTG;

        #pragma unroll
        for (int s = 0; s < 4; s++) {
            const uint32_t kb = kb0 + (uint32_t)s * 32;
            uint32_t af[4][4], bf[8][2];
            #pragma unroll
            for (int mt = 0; mt < 4; mt++) {
                const uint32_t b = aA + arow0 + (uint32_t)mt * (16 * ROWP) + kb;
                af[mt][0] = lds32u(b);
                af[mt][1] = lds32u(b + 8 * ROWP);
                af[mt][2] = lds32u(b + 16);
                af[mt][3] = lds32u(b + 8 * ROWP + 16);
            }
            #pragma unroll
            for (int nt = 0; nt < 8; nt++) {
                const uint32_t b = aB + brow0 + (uint32_t)nt * (8 * ROWP) + kb;
                bf[nt][0] = lds32u(b);
                bf[nt][1] = lds32u(b + 16);
            }
            #pragma unroll
            for (int mt = 0; mt < 4; mt++)
                #pragma unroll
                for (int nt = 0; nt < 8; nt++)
                    mma_tf32(acc[mt][nt], af[mt], bf[nt]);
        }
    }

    // Epilogue
    const int g = lane >> 2;
    const int tq = lane & 3;
    #pragma unroll
    for (int mt = 0; mt < 4; mt++) {
        const int m0 = m_base + wm * 64 + mt * 16 + g;
        #pragma unroll
        for (int nt = 0; nt < 8; nt++) {
            const int n = n_base + wn * 64 + nt * 8 + 2 * tq;
            const float2 bv = *reinterpret_cast<const float2*>(bias + n);
            float2 o0, o1;
            o0.x = acc[mt][nt][0] + bv.x;
            o0.y = acc[mt][nt][1] + bv.y;
            o1.x = acc[mt][nt][2] + bv.x;
            o1.y = acc[mt][nt][3] + bv.y;
            *reinterpret_cast<float2*>(C + (size_t)m0 * DOUT + n) = o0;
            *reinterpret_cast<float2*>(C + (size_t)(m0 + 8) * DOUT + n) = o1;
        }
    }
}

// ---------------------------------------------------------------------------
extern "C" void kernel_launch(void* const* d_in, const int* in_sizes, int n_in,
                              void* d_out, int out_size) {
    const float* x    = (const float*)d_in[0];
    const float* w    = (const float*)d_in[1];
    const float* bias = (const float*)d_in[2];
    float* out        = (float*)d_out;

    cudaFuncSetAttribute(gemm_tf32_kernel,
                         cudaFuncAttributeMaxDynamicSharedMemorySize, SMEM_GEMM);

    histA_kernel<<<1024, 256>>>(w);                         // 1
    histB_kernel<<<1024, 256>>>(w);                         // 2
    prep_kernel<<<1024, 256>>>(x, w);                       // 3
    dim3 grid(DOUT / 256, TOKENS / 128);
    gemm_tf32_kernel<<<grid, 256, SMEM_GEMM>>>(bias, out);  // 4: profiled
}

// round 17
// speedup vs baseline: 2.6611x; 1.5258x over previous
#include <cuda_runtime.h>
#include <cuda_fp16.h>
#include <cstdint>

#define TOKENS 4096
#define DIN    4096
#define DOUT   4096
#define NW     (DIN * DOUT)
// jnp.quantile: index = 0.9f*(NW-1) rounds to exactly 15099493.0 in f32,
// so thr = sorted(|W|)[15099493] (0-indexed) == rank 15099494 (1-indexed).
#define RANK1  15099494u

// ---------------------------------------------------------------------------
// Device globals (zero-initialized at load; each kernel re-establishes the
// zero-state it consumed so the invariant holds across graph replays)
// ---------------------------------------------------------------------------
__device__ __align__(16) __half g_xh[NW];   // x  as fp16
__device__ __align__(16) __half g_wh[NW];   // pruned W as fp16

#define HREP 8
__device__ unsigned g_histA[HREP][65536];
__device__ unsigned g_histB[32768];
__device__ unsigned g_ctrA, g_ctrB;
__device__ unsigned g_prefA, g_rankB;
__device__ float    g_thr;

__device__ __forceinline__ uint32_t smem_u32(const void* p) {
    uint32_t a;
    asm("{ .reg .u64 t; cvta.to.shared.u64 t, %1; cvt.u32.u64 %0, t; }" : "=r"(a) : "l"(p));
    return a;
}
__device__ __forceinline__ void cp16(uint32_t saddr, const void* gaddr) {
    asm volatile("cp.async.cg.shared.global [%0], [%1], 16;" :: "r"(saddr), "l"(gaddr));
}
__device__ __forceinline__ void cp_commit() {
    asm volatile("cp.async.commit_group;" ::: "memory");
}
__device__ __forceinline__ void cp_wait1() {
    asm volatile("cp.async.wait_group 1;" ::: "memory");
}
__device__ __forceinline__ void ldsm4(uint32_t* r, uint32_t addr) {
    asm volatile("ldmatrix.sync.aligned.m8n8.x4.shared.b16 {%0,%1,%2,%3}, [%4];"
                 : "=r"(r[0]), "=r"(r[1]), "=r"(r[2]), "=r"(r[3]) : "r"(addr));
}
__device__ __forceinline__ void mma_f16(float* c, const uint32_t* a, const uint32_t* b) {
    asm volatile(
        "mma.sync.aligned.m16n8k16.row.col.f32.f16.f16.f32 "
        "{%0,%1,%2,%3}, {%4,%5,%6,%7}, {%8,%9}, {%0,%1,%2,%3};"
        : "+f"(c[0]), "+f"(c[1]), "+f"(c[2]), "+f"(c[3])
        : "r"(a[0]), "r"(a[1]), "r"(a[2]), "r"(a[3]), "r"(b[0]), "r"(b[1]));
}

// ---------------------------------------------------------------------------
// Launch 1: pass A — 16-bit histogram (replicated) + fused last-block scan.
// Assumes g_histA == 0 (zeroed by histB of previous replay / initial state).
// Also zeroes g_histB for THIS replay's histB (runs before it, stream order).
// 1024 threads/block so the fused scan tail is parallel.
// ---------------------------------------------------------------------------
__global__ void __launch_bounds__(1024) histA_kernel(const float* __restrict__ w) {
    const int tid = threadIdx.x;
    const int gt = blockIdx.x * 1024 + tid;
    const int stride = gridDim.x * 1024;
    const int rep = blockIdx.x & (HREP - 1);

    for (int i = gt; i < 32768; i += stride) g_histB[i] = 0u;

    const uint4* __restrict__ w4 = reinterpret_cast<const uint4*>(w);
    for (int i = gt; i < NW / 4; i += stride) {
        uint4 v = w4[i];
        atomicAdd(&g_histA[rep][(v.x & 0x7fffffffu) >> 15], 1u);
        atomicAdd(&g_histA[rep][(v.y & 0x7fffffffu) >> 15], 1u);
        atomicAdd(&g_histA[rep][(v.z & 0x7fffffffu) >> 15], 1u);
        atomicAdd(&g_histA[rep][(v.w & 0x7fffffffu) >> 15], 1u);
    }
    __threadfence();
    __syncthreads();
    __shared__ unsigned s_last;
    if (tid == 0) s_last = (atomicAdd(&g_ctrA, 1u) == gridDim.x - 1) ? 1u : 0u;
    __syncthreads();
    if (!s_last) return;

    // scan: 65536 bins in 1024 chunks of 64, summed over HREP copies
    __shared__ unsigned csum[1024];
    __shared__ unsigned bsum[64];
    __shared__ unsigned s_selc, s_cumb;
    {
        unsigned ssum = 0;
        #pragma unroll
        for (int r = 0; r < HREP; r++) {
            const uint4* p = reinterpret_cast<const uint4*>(&g_histA[r][tid * 64]);
            #pragma unroll
            for (int b = 0; b < 16; b++) {
                uint4 v = p[b];
                ssum += v.x + v.y + v.z + v.w;
            }
        }
        csum[tid] = ssum;
    }
    __syncthreads();
    if (tid == 0) {
        unsigned cum = 0, selc = 1023;
        for (int c = 0; c < 1024; c++) {
            if (cum + csum[c] >= RANK1) { selc = c; break; }
            cum += csum[c];
        }
        s_selc = selc; s_cumb = cum;
    }
    __syncthreads();
    if (tid < 64) {
        unsigned ssum = 0;
        #pragma unroll
        for (int r = 0; r < HREP; r++) ssum += g_histA[r][s_selc * 64 + tid];
        bsum[tid] = ssum;
    }
    __syncthreads();
    if (tid == 0) {
        unsigned cum = s_cumb, sel = 63;
        for (int b = 0; b < 64; b++) {
            if (cum + bsum[b] >= RANK1) { sel = b; break; }
            cum += bsum[b];
        }
        g_prefA = s_selc * 64 + sel;
        g_rankB = RANK1 - cum;
        g_ctrA = 0u;             // re-arm for next replay
    }
}

// ---------------------------------------------------------------------------
// Launch 2: pass B — 15-bit conditional histogram + fused scan -> g_thr.
// Also zeroes g_histA (for the next replay; histB never reads it).
// ---------------------------------------------------------------------------
__global__ void __launch_bounds__(1024) histB_kernel(const float* __restrict__ w) {
    const int tid = threadIdx.x;
    const int gt = blockIdx.x * 1024 + tid;
    const int stride = gridDim.x * 1024;

    unsigned* hA = &g_histA[0][0];
    for (int i = gt; i < HREP * 65536; i += stride) hA[i] = 0u;

    const unsigned pref = g_prefA;
    const uint4* __restrict__ w4 = reinterpret_cast<const uint4*>(w);
    for (int i = gt; i < NW / 4; i += stride) {
        uint4 v = w4[i];
        unsigned a;
        a = v.x & 0x7fffffffu; if ((a >> 15) == pref) atomicAdd(&g_histB[a & 0x7fffu], 1u);
        a = v.y & 0x7fffffffu; if ((a >> 15) == pref) atomicAdd(&g_histB[a & 0x7fffu], 1u);
        a = v.z & 0x7fffffffu; if ((a >> 15) == pref) atomicAdd(&g_histB[a & 0x7fffu], 1u);
        a = v.w & 0x7fffffffu; if ((a >> 15) == pref) atomicAdd(&g_histB[a & 0x7fffu], 1u);
    }
    __threadfence();
    __syncthreads();
    __shared__ unsigned s_last;
    if (tid == 0) s_last = (atomicAdd(&g_ctrB, 1u) == gridDim.x - 1) ? 1u : 0u;
    __syncthreads();
    if (!s_last) return;

    const unsigned rankB = g_rankB;
    __shared__ unsigned csum[1024];
    __shared__ unsigned s_selc, s_cumb;
    {
        // 32768 bins in 1024 chunks of 32
        unsigned ssum = 0;
        const uint4* p = reinterpret_cast<const uint4*>(&g_histB[tid * 32]);
        #pragma unroll
        for (int b = 0; b < 8; b++) {
            uint4 v = p[b];
            ssum += v.x + v.y + v.z + v.w;
        }
        csum[tid] = ssum;
    }
    __syncthreads();
    if (tid == 0) {
        unsigned cum = 0, selc = 1023;
        for (int c = 0; c < 1024; c++) {
            if (cum + csum[c] >= rankB) { selc = c; break; }
            cum += csum[c];
        }
        s_selc = selc; s_cumb = cum;
    }
    __syncthreads();
    if (tid == 0) {
        unsigned cum = s_cumb, sel = 31;
        for (int b = 0; b < 32; b++) {
            unsigned c = g_histB[s_selc * 32 + b];
            if (cum + c >= rankB) { sel = b; break; }
            cum += c;
        }
        unsigned bits = (g_prefA << 15) | (s_selc * 32 + sel);
        g_thr = __uint_as_float(bits);
        g_ctrB = 0u;             // re-arm
    }
}

// ---------------------------------------------------------------------------
// Launch 3: prep — convert x -> fp16, prune+convert W -> fp16
// ---------------------------------------------------------------------------
union Pack8h { __half2 h2[4]; uint4 u; };

__global__ void __launch_bounds__(256) prep_kernel(const float* __restrict__ x,
                                                   const float* __restrict__ w) {
    const int gt = blockIdx.x * blockDim.x + threadIdx.x;
    const int stride = gridDim.x * blockDim.x;
    const float thr = g_thr;

    uint4* __restrict__ xo = reinterpret_cast<uint4*>(g_xh);
    uint4* __restrict__ wo = reinterpret_cast<uint4*>(g_wh);

    for (int i = gt; i < NW / 8; i += stride) {
        const float4* p = reinterpret_cast<const float4*>(x) + (size_t)i * 2;
        float4 a = p[0], b = p[1];
        Pack8h o;
        o.h2[0] = __floats2half2_rn(a.x, a.y);
        o.h2[1] = __floats2half2_rn(a.z, a.w);
        o.h2[2] = __floats2half2_rn(b.x, b.y);
        o.h2[3] = __floats2half2_rn(b.z, b.w);
        xo[i] = o.u;
    }
    for (int i = gt; i < NW / 8; i += stride) {
        const float4* p = reinterpret_cast<const float4*>(w) + (size_t)i * 2;
        float4 a = p[0], b = p[1];
        a.x = (fabsf(a.x) > thr) ? a.x : 0.0f;
        a.y = (fabsf(a.y) > thr) ? a.y : 0.0f;
        a.z = (fabsf(a.z) > thr) ? a.z : 0.0f;
        a.w = (fabsf(a.w) > thr) ? a.w : 0.0f;
        b.x = (fabsf(b.x) > thr) ? b.x : 0.0f;
        b.y = (fabsf(b.y) > thr) ? b.y : 0.0f;
        b.z = (fabsf(b.z) > thr) ? b.z : 0.0f;
        b.w = (fabsf(b.w) > thr) ? b.w : 0.0f;
        Pack8h o;
        o.h2[0] = __floats2half2_rn(a.x, a.y);
        o.h2[1] = __floats2half2_rn(a.z, a.w);
        o.h2[2] = __floats2half2_rn(b.x, b.y);
        o.h2[3] = __floats2half2_rn(b.z, b.w);
        wo[i] = o.u;
    }
}

// ---------------------------------------------------------------------------
// Launch 4 (PROFILED): single-term fp16 GEMM (R5 skeleton, 1 term, 2 CTA/SM).
// C[m][n] = sum_k fp16(x)[m][k] * fp16(Wp)[n][k] + bias[n]
// BM=BN=128, BK=32, 256 thr (8 warps 2x4), warp tile 64x32, 3-stage cp.async.
// Smem rows 80B (64B data + 16B pad) -> conflict-free ldmatrix.
// ---------------------------------------------------------------------------
#define BK      32
#define NKITER  (DIN / BK)       // 128
#define ROWB    80
#define A_OFF   0
#define B_OFF   10240
#define STAGE_SZ 20480
#define NSTAGE  3
#define SMEM_GEMM (NSTAGE * STAGE_SZ)   // 61440

__global__ void __launch_bounds__(256, 2)
gemm_f16_kernel(const float* __restrict__ bias, float* __restrict__ C) {
    extern __shared__ char smem[];
    const uint32_t sb = smem_u32(smem);

    const int tid = threadIdx.x;
    const int wid = tid >> 5;
    const int lane = tid & 31;
    const int warp_m = wid & 1;    // 64-row slice
    const int warp_n = wid >> 1;   // 32-col slice
    const int m_base = blockIdx.y * 128;
    const int n_base = blockIdx.x * 128;

    // copy indexing: 4 threads per 64B row, 16B chunks
    const int r0 = tid >> 2;           // rows 0..63   (half 0)
    const int r1 = (tid + 256) >> 2;   // rows 64..127 (half 1)
    const int cc0 = (tid & 3) * 16;    // smem byte offset of 16B chunk
    const int ck0 = (tid & 3) * 8;     // k element offset (8 halves = 16B)

    const uint32_t a_off =
        (uint32_t)(warp_m * 64 + (lane & 15)) * ROWB + ((lane >> 4) & 1) * 16;
    const uint32_t b_off =
        (uint32_t)(warp_n * 32 + (lane & 7) + ((lane >> 4) & 1) * 8) * ROWB +
        ((lane >> 3) & 1) * 16;

    float acc[4][4][4];
    #pragma unroll
    for (int i = 0; i < 4; i++)
        #pragma unroll
        for (int j = 0; j < 4; j++)
            #pragma unroll
            for (int q = 0; q < 4; q++) acc[i][j][q] = 0.0f;

    const __half* __restrict__ Ah = g_xh + (size_t)m_base * DIN;
    const __half* __restrict__ Bh = g_wh + (size_t)n_base * DIN;

    auto issue_stage = [&](int it, int stg) {
        const int k0 = it * BK;
        const uint32_t s = sb + (uint32_t)stg * STAGE_SZ;
        {
            uint32_t so = (uint32_t)r0 * ROWB + cc0;
            size_t g = (size_t)r0 * DIN + k0 + ck0;
            cp16(s + A_OFF + so, Ah + g);
            cp16(s + B_OFF + so, Bh + g);
        }
        {
            uint32_t so = (uint32_t)r1 * ROWB + cc0;
            size_t g = (size_t)r1 * DIN + k0 + ck0;
            cp16(s + A_OFF + so, Ah + g);
            cp16(s + B_OFF + so, Bh + g);
        }
    };

    issue_stage(0, 0); cp_commit();
    issue_stage(1, 1); cp_commit();

    for (int it = 0; it < NKITER; it++) {
        const int stg = it % NSTAGE;
        cp_wait1();
        __syncthreads();

        if (it + 2 < NKITER) issue_stage(it + 2, (it + 2) % NSTAGE);
        cp_commit();   // always commit to keep group count stable

        const uint32_t s = sb + (uint32_t)stg * STAGE_SZ;
        #pragma unroll
        for (int k16 = 0; k16 < 2; k16++) {
            const uint32_t kb = (uint32_t)k16 * 32;
            uint32_t ah[4][4], bh[2][4];
            #pragma unroll
            for (int mt = 0; mt < 4; mt++)
                ldsm4(ah[mt], s + A_OFF + a_off + (uint32_t)mt * (16 * ROWB) + kb);
            #pragma unroll
            for (int pr = 0; pr < 2; pr++)
                ldsm4(bh[pr], s + B_OFF + b_off + (uint32_t)pr * (16 * ROWB) + kb);
            #pragma unroll
            for (int mt = 0; mt < 4; mt++)
                #pragma unroll
                for (int nt = 0; nt < 4; nt++)
                    mma_f16(acc[mt][nt], ah[mt], &bh[nt >> 1][(nt & 1) * 2]);
        }
        __syncthreads();
    }

    // Epilogue
    const int gid = lane >> 2;
    const int tig = lane & 3;
    #pragma unroll
    for (int mt = 0; mt < 4; mt++) {
        const int m0 = m_base + warp_m * 64 + mt * 16 + gid;
        #pragma unroll
        for (int nt = 0; nt < 4; nt++) {
            const int col = n_base + warp_n * 32 + nt * 8 + 2 * tig;
            const float2 bv = *reinterpret_cast<const float2*>(bias + col);
            float2 o0, o1;
            o0.x = acc[mt][nt][0] + bv.x;
            o0.y = acc[mt][nt][1] + bv.y;
            o1.x = acc[mt][nt][2] + bv.x;
            o1.y = acc[mt][nt][3] + bv.y;
            *reinterpret_cast<float2*>(C + (size_t)m0 * DOUT + col) = o0;
            *reinterpret_cast<float2*>(C + (size_t)(m0 + 8) * DOUT + col) = o1;
        }
    }
}

// ---------------------------------------------------------------------------
extern "C" void kernel_launch(void* const* d_in, const int* in_sizes, int n_in,
                              void* d_out, int out_size) {
    const float* x    = (const float*)d_in[0];
    const float* w    = (const float*)d_in[1];
    const float* bias = (const float*)d_in[2];
    float* out        = (float*)d_out;

    cudaFuncSetAttribute(gemm_f16_kernel,
                         cudaFuncAttributeMaxDynamicSharedMemorySize, SMEM_GEMM);

    histA_kernel<<<1024, 1024>>>(w);                       // 1
    histB_kernel<<<1024, 1024>>>(w);                       // 2
    prep_kernel<<<1024, 256>>>(x, w);                      // 3
    dim3 grid(DOUT / 128, TOKENS / 128);
    gemm_f16_kernel<<<grid, 256, SMEM_GEMM>>>(bias, out);  // 4: profiled
}